// round 1
// baseline (speedup 1.0000x reference)
#include <cuda_runtime.h>
#include <math.h>

// CustomLoss: Voronoi phase -> 32x32 FFT2 magnitude vs Gaussian-mixture target,
// global-normalized scalar loss.
//
// GRID=16, PAD=32, RADIUS=8, SIGMA=1.5, N_SEEDS=24, B=8192.

#define NS 24
#define NT 256

// global accumulators (scratch; zeroed by init_acc every launch so the graph replays correctly)
__device__ double g_sumP2;
__device__ double g_sumT2;
__device__ double g_sumPT;
__device__ int    g_maxP;   // float bits (values >= 0, so int atomicMax works)
__device__ int    g_maxT;

__global__ void init_acc()
{
    g_sumP2 = 0.0;
    g_sumT2 = 0.0;
    g_sumPT = 0.0;
    g_maxP  = 0;
    g_maxT  = 0;
}

__global__ void __launch_bounds__(NT) loss_main(
    const float* __restrict__ output,
    const float* __restrict__ targets)
{
    __shared__ float  sx[NS], sy[NS], sz[NS];
    __shared__ float  sEx[NS][32];     // amp * exp(-(c - tx)^2 / 4.5)
    __shared__ float  sEy[NS][32];     // exp(-(r - ty)^2 / 4.5)
    __shared__ float2 sW[32];          // W[k] = exp(-2*pi*i*k/32)
    __shared__ float2 sDen[32][32];    // density
    __shared__ float2 sG[32][32];      // after row DFT
    __shared__ float  sP[32][32];      // |FFT2| (un-shifted indexing)
    __shared__ double redD[24];
    __shared__ float  redF[16];

    const int tid = threadIdx.x;
    const int b   = blockIdx.x;
    const float* op = output  + b * (NS * 3);
    const float* tp = targets + b * (NS * 3);

    // ---- load seeds ----
    if (tid < NS) {
        sx[tid] = op[3 * tid + 0];
        sy[tid] = op[3 * tid + 1];
        sz[tid] = op[3 * tid + 2];
    }
    // ---- twiddle table: W[k] = cos(-pi*k/16) + i sin(-pi*k/16) ----
    if (tid >= 32 && tid < 64) {
        int k = tid - 32;
        float s, c;
        sincospif(-(float)k * (1.0f / 16.0f), &s, &c);
        sW[k] = make_float2(c, s);
    }
    // ---- separable Gaussian factors for the target ----
    for (int t = tid; t < NS * 32; t += NT) {
        int s = t >> 5, x = t & 31;
        float tx  = tp[3 * s + 0];
        float ty  = tp[3 * s + 1];
        float amp = tp[3 * s + 2];
        float dx = (float)x - tx;
        float dy = (float)x - ty;
        sEx[s][x] = amp * expf(dx * dx * (-1.0f / 4.5f));
        sEy[s][x] = expf(dy * dy * (-1.0f / 4.5f));
    }
    __syncthreads();

    // ---- density: Voronoi labels inside radius-8 disk, phase -> exp(i*2pi*phase) ----
    // Cell (p,q) on the 32x32 padded grid. Inside disk ((p-16)^2+(q-16)^2 <= 64):
    //   i = p-8, j = q-8. If i<16 && j<16 : label = argmin_s dist; else label = 0
    //   (padding / inner-mask zeroing both yield label 0 -> phase of seed 0).
    // Outside disk: phase = 0 -> density = 1 + 0i (NOT zero!).
    for (int o = tid; o < 1024; o += NT) {
        int p = o >> 5, q = o & 31;
        int rp = p - 16, rq = q - 16;
        float ph = 0.0f;
        if (rp * rp + rq * rq <= 64) {
            int lbl = 0;
            int i = p - 8, j = q - 8;
            if (i < 16 && j < 16) {
                float fi = (float)i, fj = (float)j;
                float best = 3.0e38f;
                #pragma unroll
                for (int s = 0; s < NS; s++) {
                    float dx = fi - sx[s];
                    float dy = fj - sy[s];
                    float d  = sqrtf(dx * dx + dy * dy);   // match reference (sqrt then argmin)
                    if (d < best) { best = d; lbl = s; }
                }
            }
            ph = sz[lbl];
        }
        float sn, cs;
        sincospif(2.0f * ph, &sn, &cs);   // cos(2*pi*ph), sin(2*pi*ph) with exact range reduction
        sDen[p][q] = make_float2(cs, sn);
    }
    __syncthreads();

    // ---- row DFT: sG[p][k2] = sum_q sDen[p][q] * W[(k2*q) mod 32] ----
    // Consecutive threads share p -> sDen reads are warp broadcasts.
    for (int o = tid; o < 1024; o += NT) {
        int p = o >> 5, k2 = o & 31;
        float ar = 0.0f, ai = 0.0f;
        #pragma unroll
        for (int q = 0; q < 32; q++) {
            float2 d = sDen[p][q];
            float2 w = sW[(k2 * q) & 31];
            ar = fmaf(d.x, w.x, ar); ar = fmaf(-d.y, w.y, ar);
            ai = fmaf(d.x, w.y, ai); ai = fmaf( d.y, w.x, ai);
        }
        sG[p][k2] = make_float2(ar, ai);
    }
    __syncthreads();

    // ---- column DFT + magnitude: sP[k1][k2] = |sum_p sG[p][k2] * W[(k1*p) mod 32]| ----
    for (int o = tid; o < 1024; o += NT) {
        int k1 = o >> 5, k2 = o & 31;
        float ar = 0.0f, ai = 0.0f;
        #pragma unroll
        for (int p = 0; p < 32; p++) {
            float2 d = sG[p][k2];
            float2 w = sW[(k1 * p) & 31];
            ar = fmaf(d.x, w.x, ar); ar = fmaf(-d.y, w.y, ar);
            ai = fmaf(d.x, w.y, ai); ai = fmaf( d.y, w.x, ai);
        }
        sP[k1][k2] = sqrtf(ar * ar + ai * ai);
    }
    __syncthreads();

    // ---- target + partial reductions ----
    // pred_dp[r][c] = sP[(r+16)&31][(c+16)&31]  (output fftshift; input fftshift is
    // magnitude-invariant). T[r][c] = sum_s amp_s * ex[s][c] * ey[s][r].
    float aP2 = 0.0f, aT2 = 0.0f, aPT = 0.0f, mP = 0.0f, mT = 0.0f;
    for (int o = tid; o < 1024; o += NT) {
        int r = o >> 5, c = o & 31;
        float P = sP[(r + 16) & 31][(c + 16) & 31];
        float T = 0.0f;
        #pragma unroll
        for (int s = 0; s < NS; s++)
            T = fmaf(sEy[s][r], sEx[s][c], T);
        aP2 = fmaf(P, P, aP2);
        aT2 = fmaf(T, T, aT2);
        aPT = fmaf(P, T, aPT);
        mP = fmaxf(mP, P);
        mT = fmaxf(mT, T);
    }

    // warp reduce
    #pragma unroll
    for (int off = 16; off; off >>= 1) {
        aP2 += __shfl_down_sync(0xffffffffu, aP2, off);
        aT2 += __shfl_down_sync(0xffffffffu, aT2, off);
        aPT += __shfl_down_sync(0xffffffffu, aPT, off);
        mP = fmaxf(mP, __shfl_down_sync(0xffffffffu, mP, off));
        mT = fmaxf(mT, __shfl_down_sync(0xffffffffu, mT, off));
    }
    int w = tid >> 5, lane = tid & 31;
    if (lane == 0) {
        redD[w]      = (double)aP2;
        redD[8 + w]  = (double)aT2;
        redD[16 + w] = (double)aPT;
        redF[w]      = mP;
        redF[8 + w]  = mT;
    }
    __syncthreads();
    if (tid == 0) {
        double bP2 = 0.0, bT2 = 0.0, bPT = 0.0;
        float  bMP = 0.0f, bMT = 0.0f;
        #pragma unroll
        for (int i = 0; i < 8; i++) {
            bP2 += redD[i];
            bT2 += redD[8 + i];
            bPT += redD[16 + i];
            bMP = fmaxf(bMP, redF[i]);
            bMT = fmaxf(bMT, redF[8 + i]);
        }
        atomicAdd(&g_sumP2, bP2);
        atomicAdd(&g_sumT2, bT2);
        atomicAdd(&g_sumPT, bPT);
        atomicMax(&g_maxP, __float_as_int(bMP));
        atomicMax(&g_maxT, __float_as_int(bMT));
    }
}

__global__ void finalize(float* __restrict__ out)
{
    double SP2 = g_sumP2;
    double ST2 = g_sumT2;
    double SPT = g_sumPT;
    double Mp = (double)__int_as_float(g_maxP);
    double Mt = (double)__int_as_float(g_maxT);
    // loss = sum((P/Mp - T/Mt)^2) / sqrt(sum((P/Mp)^2) * sum((T/Mt)^2))
    //      = (SP2/Mp^2 - 2*SPT/(Mp*Mt) + ST2/Mt^2) * (Mp*Mt) / sqrt(SP2*ST2)
    double num = SP2 / (Mp * Mp) - 2.0 * SPT / (Mp * Mt) + ST2 / (Mt * Mt);
    double loss = num * (Mp * Mt) / sqrt(SP2 * ST2);
    out[0] = (float)loss;
}

extern "C" void kernel_launch(void* const* d_in, const int* in_sizes, int n_in,
                              void* d_out, int out_size)
{
    const float* output  = (const float*)d_in[0];
    const float* targets = (const float*)d_in[1];
    int B = in_sizes[0] / (NS * 3);

    init_acc<<<1, 1>>>();
    loss_main<<<B, NT>>>(output, targets);
    finalize<<<1, 1>>>((float*)d_out);
}

// round 2
// speedup vs baseline: 2.8361x; 2.8361x over previous
#include <cuda_runtime.h>
#include <math.h>

// CustomLoss: Voronoi phase -> 32x32 FFT2 magnitude vs Gaussian-mixture target,
// global-normalized scalar loss. GRID=16, PAD=32, RADIUS=8, SIGMA=1.5, NS=24, B=8192.
//
// R2: warp-shuffle radix-2 DIF FFT (5 stages, twiddles in registers),
// density computed in registers, single padded transpose buffer.

#define NS 24
#define NT 256

__device__ double g_sumP2;
__device__ double g_sumT2;
__device__ double g_sumPT;
__device__ int    g_maxP;   // float bits (non-negative -> int atomicMax works)
__device__ int    g_maxT;

__global__ void init_acc()
{
    g_sumP2 = 0.0;
    g_sumT2 = 0.0;
    g_sumPT = 0.0;
    g_maxP  = 0;
    g_maxT  = 0;
}

__global__ void __launch_bounds__(NT) loss_main(
    const float* __restrict__ output,
    const float* __restrict__ targets)
{
    __shared__ float  sx[NS], sy[NS], sz[NS];
    __shared__ float  sEx[NS][32];     // amp * exp(-(c - tx)^2 / 4.5)
    __shared__ float  sEy[NS][32];     // exp(-(r - ty)^2 / 4.5)
    __shared__ float  sGr[32][33];     // transpose buffer (re), padded
    __shared__ float  sGi[32][33];     // transpose buffer (im), padded
    __shared__ double redD[24];
    __shared__ float  redF[16];

    const int tid  = threadIdx.x;
    const int w    = tid >> 5;
    const int lane = tid & 31;
    const int b    = blockIdx.x;
    const float* op = output  + b * (NS * 3);
    const float* tp = targets + b * (NS * 3);

    // ---- load seeds ----
    if (tid < NS) {
        sx[tid] = op[3 * tid + 0];
        sy[tid] = op[3 * tid + 1];
        sz[tid] = op[3 * tid + 2];
    }
    // ---- separable Gaussian factors for the target ----
    for (int t = tid; t < NS * 32; t += NT) {
        int s = t >> 5, x = t & 31;
        float tx  = tp[3 * s + 0];
        float ty  = tp[3 * s + 1];
        float amp = tp[3 * s + 2];
        float dx = (float)x - tx;
        float dy = (float)x - ty;
        sEx[s][x] = amp * expf(dx * dx * (-1.0f / 4.5f));
        sEy[s][x] = expf(dy * dy * (-1.0f / 4.5f));
    }

    // ---- per-lane twiddles for 5 DIF stages (W_32 = e^{-2*pi*i/32}) ----
    // stage st: h = 16>>st; lower lanes (lane&h) use W_32^{(lane&(h-1))<<st}, upper (1,0)
    float twr[5], twi[5];
    #pragma unroll
    for (int st = 0; st < 5; st++) {
        int h = 16 >> st;
        int idx = (lane & h) ? ((lane & (h - 1)) << st) : 0;
        float s, c;
        sincospif(-(float)idx * (1.0f / 16.0f), &s, &c);
        twr[st] = c; twi[st] = s;
    }

    __syncthreads();

    // ============ ROW PASS ============
    // Warp w handles rows p = w + 8m (m=0..3); lane = column q.
    // Density in registers; inside disk ((p-16)^2+(q-16)^2 <= 64):
    //   i=p-8, j=q-8; if i<16 && j<16 -> Voronoi argmin over d^2 (monotone vs sqrt),
    //   else label 0. Phase -> exp(i*2*pi*phase). Outside disk: 1 + 0i.
    float rr[4], ri[4];
    {
        const int rq = lane - 16;
        const int rq2 = rq * rq;
        const float fj = (float)(lane - 8);
        #pragma unroll
        for (int m = 0; m < 4; m++) {
            int p = w + 8 * m;
            int rp = p - 16;
            float ph = 0.0f;
            if (rp * rp + rq2 <= 64) {
                int lbl = 0;
                if (p < 24 && lane < 24) {
                    float fi = (float)(p - 8);
                    float best = 3.0e38f;
                    #pragma unroll
                    for (int s = 0; s < NS; s++) {
                        float dx = fi - sx[s];
                        float dy = fj - sy[s];
                        float d2 = fmaf(dx, dx, dy * dy);
                        if (d2 < best) { best = d2; lbl = s; }
                    }
                }
                ph = sz[lbl];
            }
            float sn, cs;
            sincospif(2.0f * ph, &sn, &cs);
            rr[m] = cs; ri[m] = sn;
        }
    }

    // 5-stage radix-2 DIF FFT across lanes (output in bit-reversed lane order)
    #pragma unroll
    for (int st = 0; st < 5; st++) {
        int h = 16 >> st;
        float sg = (lane & h) ? -1.0f : 1.0f;
        float wr = twr[st], wi = twi[st];
        #pragma unroll
        for (int m = 0; m < 4; m++) {
            float o_r = __shfl_xor_sync(0xffffffffu, rr[m], h);
            float o_i = __shfl_xor_sync(0xffffffffu, ri[m], h);
            float ur = fmaf(sg, rr[m], o_r);
            float ui = fmaf(sg, ri[m], o_i);
            rr[m] = fmaf(ur, wr, -ui * wi);
            ri[m] = fmaf(ur, wi,  ui * wr);
        }
    }

    // store transposed at true frequency k2 = brev5(lane); (brev(l)+p) mod 32 distinct -> conflict-free
    {
        int k2 = __brev(lane) >> 27;
        #pragma unroll
        for (int m = 0; m < 4; m++) {
            int p = w + 8 * m;
            sGr[k2][p] = rr[m];
            sGi[k2][p] = ri[m];
        }
    }
    __syncthreads();

    // ============ COLUMN PASS ============
    // Warp w handles columns k2 = w + 8m; lane = row index p.
    float cr[4], ci[4];
    #pragma unroll
    for (int m = 0; m < 4; m++) {
        int k2 = w + 8 * m;
        cr[m] = sGr[k2][lane];
        ci[m] = sGi[k2][lane];
    }

    #pragma unroll
    for (int st = 0; st < 5; st++) {
        int h = 16 >> st;
        float sg = (lane & h) ? -1.0f : 1.0f;
        float wr = twr[st], wi = twi[st];
        #pragma unroll
        for (int m = 0; m < 4; m++) {
            float o_r = __shfl_xor_sync(0xffffffffu, cr[m], h);
            float o_i = __shfl_xor_sync(0xffffffffu, ci[m], h);
            float ur = fmaf(sg, cr[m], o_r);
            float ui = fmaf(sg, ci[m], o_i);
            cr[m] = fmaf(ur, wr, -ui * wi);
            ci[m] = fmaf(ur, wi,  ui * wr);
        }
    }

    // ---- magnitude + target + accumulate ----
    // Lane holds freq k1 = brev5(lane) for each of its 4 columns k2.
    // fftshift: position (r,c) = (k1^16, k2^16). Input fftshift is magnitude-invariant.
    float aP2 = 0.0f, aT2 = 0.0f, aPT = 0.0f, mP = 0.0f, mT = 0.0f;
    {
        int k1 = __brev(lane) >> 27;
        int r  = k1 ^ 16;
        float P[4], T[4];
        #pragma unroll
        for (int m = 0; m < 4; m++) {
            P[m] = sqrtf(fmaf(cr[m], cr[m], ci[m] * ci[m]));
            T[m] = 0.0f;
        }
        #pragma unroll
        for (int s = 0; s < NS; s++) {
            float ey = sEy[s][r];
            #pragma unroll
            for (int m = 0; m < 4; m++) {
                int c = (w + 8 * m) ^ 16;
                T[m] = fmaf(ey, sEx[s][c], T[m]);
            }
        }
        #pragma unroll
        for (int m = 0; m < 4; m++) {
            aP2 = fmaf(P[m], P[m], aP2);
            aT2 = fmaf(T[m], T[m], aT2);
            aPT = fmaf(P[m], T[m], aPT);
            mP = fmaxf(mP, P[m]);
            mT = fmaxf(mT, T[m]);
        }
    }

    // warp reduce
    #pragma unroll
    for (int off = 16; off; off >>= 1) {
        aP2 += __shfl_down_sync(0xffffffffu, aP2, off);
        aT2 += __shfl_down_sync(0xffffffffu, aT2, off);
        aPT += __shfl_down_sync(0xffffffffu, aPT, off);
        mP = fmaxf(mP, __shfl_down_sync(0xffffffffu, mP, off));
        mT = fmaxf(mT, __shfl_down_sync(0xffffffffu, mT, off));
    }
    if (lane == 0) {
        redD[w]      = (double)aP2;
        redD[8 + w]  = (double)aT2;
        redD[16 + w] = (double)aPT;
        redF[w]      = mP;
        redF[8 + w]  = mT;
    }
    __syncthreads();
    if (tid == 0) {
        double bP2 = 0.0, bT2 = 0.0, bPT = 0.0;
        float  bMP = 0.0f, bMT = 0.0f;
        #pragma unroll
        for (int i = 0; i < 8; i++) {
            bP2 += redD[i];
            bT2 += redD[8 + i];
            bPT += redD[16 + i];
            bMP = fmaxf(bMP, redF[i]);
            bMT = fmaxf(bMT, redF[8 + i]);
        }
        atomicAdd(&g_sumP2, bP2);
        atomicAdd(&g_sumT2, bT2);
        atomicAdd(&g_sumPT, bPT);
        atomicMax(&g_maxP, __float_as_int(bMP));
        atomicMax(&g_maxT, __float_as_int(bMT));
    }
}

__global__ void finalize(float* __restrict__ out)
{
    double SP2 = g_sumP2;
    double ST2 = g_sumT2;
    double SPT = g_sumPT;
    double Mp = (double)__int_as_float(g_maxP);
    double Mt = (double)__int_as_float(g_maxT);
    // loss = (SP2/Mp^2 - 2*SPT/(Mp*Mt) + ST2/Mt^2) * (Mp*Mt) / sqrt(SP2*ST2)
    double num = SP2 / (Mp * Mp) - 2.0 * SPT / (Mp * Mt) + ST2 / (Mt * Mt);
    double loss = num * (Mp * Mt) / sqrt(SP2 * ST2);
    out[0] = (float)loss;
}

extern "C" void kernel_launch(void* const* d_in, const int* in_sizes, int n_in,
                              void* d_out, int out_size)
{
    const float* output  = (const float*)d_in[0];
    const float* targets = (const float*)d_in[1];
    int B = in_sizes[0] / (NS * 3);

    init_acc<<<1, 1>>>();
    loss_main<<<B, NT>>>(output, targets);
    finalize<<<1, 1>>>((float*)d_out);
}

// round 3
// speedup vs baseline: 3.9514x; 1.3933x over previous
#include <cuda_runtime.h>
#include <math.h>

// CustomLoss: Voronoi phase -> 32x32 FFT2 magnitude vs Gaussian-mixture target,
// global-normalized scalar loss. GRID=16, PAD=32, RADIUS=8, SIGMA=1.5, NS=24, B=8192.
//
// R3: no init kernel (finalize self-resets), smem twiddle table, precomputed
// per-seed phase cos/sin, packed-key Voronoi argmin (m=1,2 only), identity last
// FFT stage, float4 ex reads in the target sum.

#define NS 24
#define NT 256

__device__ double g_sumP2 = 0.0;
__device__ double g_sumT2 = 0.0;
__device__ double g_sumPT = 0.0;
__device__ int    g_maxP  = 0;   // float bits (non-negative -> int atomicMax works)
__device__ int    g_maxT  = 0;

__global__ void __launch_bounds__(NT) loss_main(
    const float* __restrict__ output,
    const float* __restrict__ targets)
{
    __shared__ float  sxs[NS], sys[NS];
    __shared__ float2 sCS[NS];                    // (cos 2pi z, sin 2pi z) per seed
    __shared__ __align__(16) float sExP[NS * 32]; // permuted: [s][ (x&7)*4 + (x>>3) ]
    __shared__ float  sEy[NS][32];                // exp(-(r - ty)^2 / 4.5)
    __shared__ float2 sTw[32];                    // W_32^k = exp(-2*pi*i*k/32)
    __shared__ float  sGr[32][33];                // transpose buffer (re), padded
    __shared__ float  sGi[32][33];                // transpose buffer (im), padded
    __shared__ double redD[24];
    __shared__ float  redF[16];

    const int tid  = threadIdx.x;
    const int w    = tid >> 5;
    const int lane = tid & 31;
    const int b    = blockIdx.x;
    const float* op = output  + b * (NS * 3);
    const float* tp = targets + b * (NS * 3);

    // ---- seeds + per-seed phase cos/sin ----
    if (tid < NS) {
        sxs[tid] = op[3 * tid + 0];
        sys[tid] = op[3 * tid + 1];
        float z  = op[3 * tid + 2];
        float s, c;
        sincospif(2.0f * z, &s, &c);
        sCS[tid] = make_float2(c, s);
    }
    // ---- twiddle table ----
    if (tid >= 32 && tid < 64) {
        int k = tid - 32;
        float s, c;
        sincospif(-(float)k * (1.0f / 16.0f), &s, &c);
        sTw[k] = make_float2(c, s);
    }
    // ---- separable Gaussian factors for the target ----
    for (int t = tid; t < NS * 32; t += NT) {
        int s = t >> 5, x = t & 31;
        float tx  = tp[3 * s + 0];
        float ty  = tp[3 * s + 1];
        float amp = tp[3 * s + 2];
        float dx = (float)x - tx;
        float dy = (float)x - ty;
        sExP[(s << 5) + ((x & 7) << 2) + (x >> 3)] = amp * expf(dx * dx * (-1.0f / 4.5f));
        sEy[s][x] = expf(dy * dy * (-1.0f / 4.5f));
    }
    __syncthreads();

    // ---- per-lane twiddles for stages 0..3 (stage 4 has identity twiddles) ----
    float twr[4], twi[4];
    #pragma unroll
    for (int st = 0; st < 4; st++) {
        int h = 16 >> st;
        int idx = (lane & h) ? ((lane & (h - 1)) << st) : 0;
        float2 tw = sTw[idx];
        twr[st] = tw.x; twi[st] = tw.y;
    }

    // ============ DENSITY (rows p = w + 8m, column q = lane) ============
    // m=0: p=w<8 -> always outside disk -> (1,0).
    // m=3: p=w+24 -> inside disk only at (p=24,q=16) -> label 0.
    // m=1,2: Voronoi argmin over 24 seeds (packed float-bits|idx key, integer min).
    float rr[4], ri[4];
    {
        const int rq  = lane - 16;
        const int rq2 = rq * rq;
        const float fj  = (float)(lane - 8);
        const float fi1 = (float)w;          // i for m=1 (p=w+8)
        int best1 = 0x7fffffff, best2 = 0x7fffffff;
        #pragma unroll
        for (int s = 0; s < NS; s++) {
            float sx = sxs[s], sy = sys[s];
            float dy  = fj - sy;
            float dyy = dy * dy;
            float dx1 = fi1 - sx;
            float dx2 = dx1 + 8.0f;
            float d21 = fmaf(dx1, dx1, dyy);
            float d22 = fmaf(dx2, dx2, dyy);
            int k1 = (__float_as_int(d21) & 0xffffffe0) | s;
            int k2 = (__float_as_int(d22) & 0xffffffe0) | s;
            best1 = min(best1, k1);
            best2 = min(best2, k2);
        }
        int lbl1 = (lane < 24) ? (best1 & 31) : 0;
        int lbl2 = (lane < 24) ? (best2 & 31) : 0;
        float2 cs1 = sCS[lbl1];
        float2 cs2 = sCS[lbl2];
        float2 cs0 = sCS[0];

        // m=0
        rr[0] = 1.0f; ri[0] = 0.0f;
        // m=1: rp = w-8
        {
            int rp = w - 8;
            bool in = (rp * rp + rq2 <= 64);
            rr[1] = in ? cs1.x : 1.0f;
            ri[1] = in ? cs1.y : 0.0f;
        }
        // m=2: rp = w
        {
            bool in = (w * w + rq2 <= 64);
            rr[2] = in ? cs2.x : 1.0f;
            ri[2] = in ? cs2.y : 0.0f;
        }
        // m=3: rp = w+8
        {
            int rp = w + 8;
            bool in = (rp * rp + rq2 <= 64);
            rr[3] = in ? cs0.x : 1.0f;
            ri[3] = in ? cs0.y : 0.0f;
        }
    }

    // ============ ROW FFT (5-stage radix-2 DIF across lanes) ============
    #pragma unroll
    for (int st = 0; st < 4; st++) {
        int h = 16 >> st;
        float sg = (lane & h) ? -1.0f : 1.0f;
        float wr = twr[st], wi = twi[st];
        #pragma unroll
        for (int m = 0; m < 4; m++) {
            float o_r = __shfl_xor_sync(0xffffffffu, rr[m], h);
            float o_i = __shfl_xor_sync(0xffffffffu, ri[m], h);
            float ur = fmaf(sg, rr[m], o_r);
            float ui = fmaf(sg, ri[m], o_i);
            rr[m] = fmaf(ur, wr, -ui * wi);
            ri[m] = fmaf(ur, wi,  ui * wr);
        }
    }
    {   // stage 4: h=1, identity twiddles
        float sg = (lane & 1) ? -1.0f : 1.0f;
        #pragma unroll
        for (int m = 0; m < 4; m++) {
            float o_r = __shfl_xor_sync(0xffffffffu, rr[m], 1);
            float o_i = __shfl_xor_sync(0xffffffffu, ri[m], 1);
            rr[m] = fmaf(sg, rr[m], o_r);
            ri[m] = fmaf(sg, ri[m], o_i);
        }
    }

    // store transposed at true frequency k2 = brev5(lane); conflict-free
    {
        int k2 = __brev(lane) >> 27;
        #pragma unroll
        for (int m = 0; m < 4; m++) {
            int p = w + 8 * m;
            sGr[k2][p] = rr[m];
            sGi[k2][p] = ri[m];
        }
    }
    __syncthreads();

    // ============ COLUMN FFT ============
    float cr[4], ci[4];
    #pragma unroll
    for (int m = 0; m < 4; m++) {
        int k2 = w + 8 * m;
        cr[m] = sGr[k2][lane];
        ci[m] = sGi[k2][lane];
    }
    #pragma unroll
    for (int st = 0; st < 4; st++) {
        int h = 16 >> st;
        float sg = (lane & h) ? -1.0f : 1.0f;
        float wr = twr[st], wi = twi[st];
        #pragma unroll
        for (int m = 0; m < 4; m++) {
            float o_r = __shfl_xor_sync(0xffffffffu, cr[m], h);
            float o_i = __shfl_xor_sync(0xffffffffu, ci[m], h);
            float ur = fmaf(sg, cr[m], o_r);
            float ui = fmaf(sg, ci[m], o_i);
            cr[m] = fmaf(ur, wr, -ui * wi);
            ci[m] = fmaf(ur, wi,  ui * wr);
        }
    }
    {   // stage 4: identity twiddles
        float sg = (lane & 1) ? -1.0f : 1.0f;
        #pragma unroll
        for (int m = 0; m < 4; m++) {
            float o_r = __shfl_xor_sync(0xffffffffu, cr[m], 1);
            float o_i = __shfl_xor_sync(0xffffffffu, ci[m], 1);
            cr[m] = fmaf(sg, cr[m], o_r);
            ci[m] = fmaf(sg, ci[m], o_i);
        }
    }

    // ---- magnitude + target + accumulate ----
    // Lane's frequency k1 = brev5(lane); shifted position (r,c) = (k1^16, (w+8m)^16).
    // c_m = (w+8m)^16 = w+8*(m^2): float4 read gives ex[s][w+8j] in component j.
    float aP2 = 0.0f, aT2 = 0.0f, aPT = 0.0f, mP = 0.0f, mT = 0.0f;
    {
        int r = (__brev(lane) >> 27) ^ 16;
        float P[4], T[4];
        #pragma unroll
        for (int m = 0; m < 4; m++) {
            P[m] = sqrtf(fmaf(cr[m], cr[m], ci[m] * ci[m]));
            T[m] = 0.0f;
        }
        #pragma unroll
        for (int s = 0; s < NS; s++) {
            float  ey = sEy[s][r];
            float4 V  = *reinterpret_cast<const float4*>(&sExP[(s << 5) + (w << 2)]);
            T[0] = fmaf(ey, V.z, T[0]);   // m=0 -> component m^2 = 2
            T[1] = fmaf(ey, V.w, T[1]);   // m=1 -> 3
            T[2] = fmaf(ey, V.x, T[2]);   // m=2 -> 0
            T[3] = fmaf(ey, V.y, T[3]);   // m=3 -> 1
        }
        #pragma unroll
        for (int m = 0; m < 4; m++) {
            aP2 = fmaf(P[m], P[m], aP2);
            aT2 = fmaf(T[m], T[m], aT2);
            aPT = fmaf(P[m], T[m], aPT);
            mP = fmaxf(mP, P[m]);
            mT = fmaxf(mT, T[m]);
        }
    }

    // warp reduce
    #pragma unroll
    for (int off = 16; off; off >>= 1) {
        aP2 += __shfl_down_sync(0xffffffffu, aP2, off);
        aT2 += __shfl_down_sync(0xffffffffu, aT2, off);
        aPT += __shfl_down_sync(0xffffffffu, aPT, off);
        mP = fmaxf(mP, __shfl_down_sync(0xffffffffu, mP, off));
        mT = fmaxf(mT, __shfl_down_sync(0xffffffffu, mT, off));
    }
    if (lane == 0) {
        redD[w]      = (double)aP2;
        redD[8 + w]  = (double)aT2;
        redD[16 + w] = (double)aPT;
        redF[w]      = mP;
        redF[8 + w]  = mT;
    }
    __syncthreads();
    if (tid == 0) {
        double bP2 = 0.0, bT2 = 0.0, bPT = 0.0;
        float  bMP = 0.0f, bMT = 0.0f;
        #pragma unroll
        for (int i = 0; i < 8; i++) {
            bP2 += redD[i];
            bT2 += redD[8 + i];
            bPT += redD[16 + i];
            bMP = fmaxf(bMP, redF[i]);
            bMT = fmaxf(bMT, redF[8 + i]);
        }
        atomicAdd(&g_sumP2, bP2);
        atomicAdd(&g_sumT2, bT2);
        atomicAdd(&g_sumPT, bPT);
        atomicMax(&g_maxP, __float_as_int(bMP));
        atomicMax(&g_maxT, __float_as_int(bMT));
    }
}

__global__ void finalize(float* __restrict__ out)
{
    double SP2 = g_sumP2;
    double ST2 = g_sumT2;
    double SPT = g_sumPT;
    double Mp = (double)__int_as_float(g_maxP);
    double Mt = (double)__int_as_float(g_maxT);
    // loss = (SP2/Mp^2 - 2*SPT/(Mp*Mt) + ST2/Mt^2) * (Mp*Mt) / sqrt(SP2*ST2)
    double num = SP2 / (Mp * Mp) - 2.0 * SPT / (Mp * Mt) + ST2 / (Mt * Mt);
    double loss = num * (Mp * Mt) / sqrt(SP2 * ST2);
    out[0] = (float)loss;

    // self-reset accumulators for the next graph replay (initial state is the
    // static zero-initialization, so every launch sees identical state)
    g_sumP2 = 0.0;
    g_sumT2 = 0.0;
    g_sumPT = 0.0;
    g_maxP  = 0;
    g_maxT  = 0;
}

extern "C" void kernel_launch(void* const* d_in, const int* in_sizes, int n_in,
                              void* d_out, int out_size)
{
    const float* output  = (const float*)d_in[0];
    const float* targets = (const float*)d_in[1];
    int B = in_sizes[0] / (NS * 3);

    loss_main<<<B, NT>>>(output, targets);
    finalize<<<1, 1>>>((float*)d_out);
}

// round 6
// speedup vs baseline: 4.1046x; 1.0388x over previous
#include <cuda_runtime.h>
#include <math.h>

// CustomLoss: Voronoi phase -> 32x32 FFT2 magnitude vs Gaussian-mixture target,
// global-normalized scalar loss. GRID=16, PAD=32, RADIUS=8, SIGMA=1.5, NS=24, B=8192.
//
// R5 (== R4 resubmit after infra failure): single fused kernel (last block
// finalizes + self-resets), analytic row FFTs for the 16 trivial rows,
// float4-packed linearized Voronoi argmin.

#define NS 24
#define NT 256

__device__ double   g_sumP2 = 0.0;
__device__ double   g_sumT2 = 0.0;
__device__ double   g_sumPT = 0.0;
__device__ int      g_maxQ  = 0;   // float bits of max(P^2) (non-negative)
__device__ int      g_maxT  = 0;   // float bits of max(T)
__device__ unsigned g_count = 0;

__global__ void __launch_bounds__(NT) loss_main(
    const float* __restrict__ output,
    const float* __restrict__ targets,
    float* __restrict__ out)
{
    __shared__ __align__(16) float4 sSeed[NS];    // (-2sx, -2sy, sx^2+sy^2+512, 0)
    __shared__ float2 sCS[NS];                    // (cos 2pi z, sin 2pi z) per seed
    __shared__ __align__(16) float sExP[NS * 32]; // permuted: [s][ (x&7)*4 + (x>>3) ]
    __shared__ float  sEy[NS][32];                // exp(-(r - ty)^2 / 4.5)
    __shared__ float2 sTw[32];                    // W_32^k = exp(-2*pi*i*k/32)
    __shared__ float  sGr[32][33];                // transpose buffer (re), padded
    __shared__ float  sGi[32][33];                // transpose buffer (im), padded
    __shared__ double redD[24];
    __shared__ float  redF[16];

    const int tid  = threadIdx.x;
    const int w    = tid >> 5;
    const int lane = tid & 31;
    const int b    = blockIdx.x;
    const float* op = output  + b * (NS * 3);
    const float* tp = targets + b * (NS * 3);

    // ---- seeds (packed linear form) + per-seed phase cos/sin ----
    if (tid < NS) {
        float sx = op[3 * tid + 0];
        float sy = op[3 * tid + 1];
        float z  = op[3 * tid + 2];
        sSeed[tid] = make_float4(-2.0f * sx, -2.0f * sy,
                                 fmaf(sx, sx, fmaf(sy, sy, 512.0f)), 0.0f);
        float s, c;
        sincospif(2.0f * z, &s, &c);
        sCS[tid] = make_float2(c, s);
    }
    // ---- twiddle table ----
    if (tid >= 32 && tid < 64) {
        int k = tid - 32;
        float s, c;
        sincospif(-(float)k * (1.0f / 16.0f), &s, &c);
        sTw[k] = make_float2(c, s);
    }
    // ---- separable Gaussian factors for the target ----
    for (int t = tid; t < NS * 32; t += NT) {
        int s = t >> 5, x = t & 31;
        float tx  = tp[3 * s + 0];
        float ty  = tp[3 * s + 1];
        float amp = tp[3 * s + 2];
        float dx = (float)x - tx;
        float dy = (float)x - ty;
        sExP[(s << 5) + ((x & 7) << 2) + (x >> 3)] = amp * expf(dx * dx * (-1.0f / 4.5f));
        sEy[s][x] = expf(dy * dy * (-1.0f / 4.5f));
    }
    __syncthreads();

    // ---- per-lane twiddles for stages 0..3 (stage 4 has identity twiddles) ----
    float twr[4], twi[4];
    #pragma unroll
    for (int st = 0; st < 4; st++) {
        int h = 16 >> st;
        int idx = (lane & h) ? ((lane & (h - 1)) << st) : 0;
        float2 tw = sTw[idx];
        twr[st] = tw.x; twi[st] = tw.y;
    }

    // ============ DENSITY for rows 8..23 only (m=1: p=w+8, m=2: p=w+16) ============
    // argmin_s d^2 == argmin_s (fi*(-2sx) + fj*(-2sy) + sx^2+sy^2) ; +512 bias keeps >0.
    // val2 = val1 + 8*(-2sx). Packed float-bits|idx key, integer min.
    float rr[2], ri[2];
    {
        const int   rq  = lane - 16;
        const int   rq2 = rq * rq;
        const float fj  = (float)(lane - 8);
        const float fi1 = (float)w;          // i for m=1 (p=w+8)
        int best1 = 0x7fffffff, best2 = 0x7fffffff;
        #pragma unroll
        for (int s = 0; s < NS; s++) {
            float4 S = sSeed[s];
            float t0   = fmaf(fj, S.y, S.z);
            float val1 = fmaf(fi1, S.x, t0);
            float val2 = fmaf(8.0f, S.x, val1);
            int k1 = (__float_as_int(val1) & 0xffffffe0) | s;
            int k2 = (__float_as_int(val2) & 0xffffffe0) | s;
            best1 = min(best1, k1);
            best2 = min(best2, k2);
        }
        int lbl1 = (lane < 24) ? (best1 & 31) : 0;
        int lbl2 = (lane < 24) ? (best2 & 31) : 0;
        float2 cs1 = sCS[lbl1];
        float2 cs2 = sCS[lbl2];
        {   // m=1: rp = w-8
            int rp = w - 8;
            bool in = (rp * rp + rq2 <= 64);
            rr[0] = in ? cs1.x : 1.0f;
            ri[0] = in ? cs1.y : 0.0f;
        }
        {   // m=2: rp = w
            bool in = (w * w + rq2 <= 64);
            rr[1] = in ? cs2.x : 1.0f;
            ri[1] = in ? cs2.y : 0.0f;
        }
    }

    // ---- analytic row FFTs for rows 0..7 and 24..31 ----
    // All-ones row -> 32*delta_{k2,0}. Row 24: + (cs0-1)*(-1)^{k2} (cell q=16, label 0).
    {
        float dc = (lane == 0) ? 32.0f : 0.0f;
        // row w (0..7)
        sGr[lane][w] = dc;
        sGi[lane][w] = 0.0f;
        // row 24+w
        if (w == 0) {
            float2 cs0 = sCS[0];
            float sg = (lane & 1) ? -1.0f : 1.0f;
            sGr[lane][24] = dc + (cs0.x - 1.0f) * sg;
            sGi[lane][24] = cs0.y * sg;
        } else {
            sGr[lane][24 + w] = dc;
            sGi[lane][24 + w] = 0.0f;
        }
    }

    // ============ ROW FFT (rows 8..23; 5-stage radix-2 DIF across lanes) ============
    #pragma unroll
    for (int st = 0; st < 4; st++) {
        int h = 16 >> st;
        float sg = (lane & h) ? -1.0f : 1.0f;
        float wr = twr[st], wi = twi[st];
        #pragma unroll
        for (int m = 0; m < 2; m++) {
            float o_r = __shfl_xor_sync(0xffffffffu, rr[m], h);
            float o_i = __shfl_xor_sync(0xffffffffu, ri[m], h);
            float ur = fmaf(sg, rr[m], o_r);
            float ui = fmaf(sg, ri[m], o_i);
            rr[m] = fmaf(ur, wr, -ui * wi);
            ri[m] = fmaf(ur, wi,  ui * wr);
        }
    }
    {   // stage 4: h=1, identity twiddles
        float sg = (lane & 1) ? -1.0f : 1.0f;
        #pragma unroll
        for (int m = 0; m < 2; m++) {
            float o_r = __shfl_xor_sync(0xffffffffu, rr[m], 1);
            float o_i = __shfl_xor_sync(0xffffffffu, ri[m], 1);
            rr[m] = fmaf(sg, rr[m], o_r);
            ri[m] = fmaf(sg, ri[m], o_i);
        }
    }

    // store transposed at true frequency k2 = brev5(lane); conflict-free
    {
        int k2 = __brev(lane) >> 27;
        sGr[k2][w + 8]  = rr[0];
        sGi[k2][w + 8]  = ri[0];
        sGr[k2][w + 16] = rr[1];
        sGi[k2][w + 16] = ri[1];
    }
    __syncthreads();

    // ============ COLUMN FFT (4 columns per thread: k2 = w + 8m) ============
    float cr[4], ci[4];
    #pragma unroll
    for (int m = 0; m < 4; m++) {
        int k2 = w + 8 * m;
        cr[m] = sGr[k2][lane];
        ci[m] = sGi[k2][lane];
    }
    #pragma unroll
    for (int st = 0; st < 4; st++) {
        int h = 16 >> st;
        float sg = (lane & h) ? -1.0f : 1.0f;
        float wr = twr[st], wi = twi[st];
        #pragma unroll
        for (int m = 0; m < 4; m++) {
            float o_r = __shfl_xor_sync(0xffffffffu, cr[m], h);
            float o_i = __shfl_xor_sync(0xffffffffu, ci[m], h);
            float ur = fmaf(sg, cr[m], o_r);
            float ui = fmaf(sg, ci[m], o_i);
            cr[m] = fmaf(ur, wr, -ui * wi);
            ci[m] = fmaf(ur, wi,  ui * wr);
        }
    }
    {   // stage 4: identity twiddles
        float sg = (lane & 1) ? -1.0f : 1.0f;
        #pragma unroll
        for (int m = 0; m < 4; m++) {
            float o_r = __shfl_xor_sync(0xffffffffu, cr[m], 1);
            float o_i = __shfl_xor_sync(0xffffffffu, ci[m], 1);
            cr[m] = fmaf(sg, cr[m], o_r);
            ci[m] = fmaf(sg, ci[m], o_i);
        }
    }

    // ---- magnitude + target + accumulate ----
    // Lane's frequency k1 = brev5(lane); shifted position (r,c) = (k1^16, (w+8m)^16).
    // c_m = (w+8m)^16 = w+8*(m^2): float4 read gives ex[s][w+8j] in component j.
    float aP2 = 0.0f, aT2 = 0.0f, aPT = 0.0f, mQ = 0.0f, mT = 0.0f;
    {
        int r = (__brev(lane) >> 27) ^ 16;
        float Q[4], P[4], T[4];
        #pragma unroll
        for (int m = 0; m < 4; m++) {
            Q[m] = fmaf(cr[m], cr[m], ci[m] * ci[m]);
            P[m] = sqrtf(Q[m]);
            T[m] = 0.0f;
        }
        #pragma unroll
        for (int s = 0; s < NS; s++) {
            float  ey = sEy[s][r];
            float4 V  = *reinterpret_cast<const float4*>(&sExP[(s << 5) + (w << 2)]);
            T[0] = fmaf(ey, V.z, T[0]);   // m=0 -> component m^2 = 2
            T[1] = fmaf(ey, V.w, T[1]);   // m=1 -> 3
            T[2] = fmaf(ey, V.x, T[2]);   // m=2 -> 0
            T[3] = fmaf(ey, V.y, T[3]);   // m=3 -> 1
        }
        #pragma unroll
        for (int m = 0; m < 4; m++) {
            aP2 += Q[m];
            aT2 = fmaf(T[m], T[m], aT2);
            aPT = fmaf(P[m], T[m], aPT);
            mQ = fmaxf(mQ, Q[m]);
            mT = fmaxf(mT, T[m]);
        }
    }

    // warp reduce
    #pragma unroll
    for (int off = 16; off; off >>= 1) {
        aP2 += __shfl_down_sync(0xffffffffu, aP2, off);
        aT2 += __shfl_down_sync(0xffffffffu, aT2, off);
        aPT += __shfl_down_sync(0xffffffffu, aPT, off);
        mQ = fmaxf(mQ, __shfl_down_sync(0xffffffffu, mQ, off));
        mT = fmaxf(mT, __shfl_down_sync(0xffffffffu, mT, off));
    }
    if (lane == 0) {
        redD[w]      = (double)aP2;
        redD[8 + w]  = (double)aT2;
        redD[16 + w] = (double)aPT;
        redF[w]      = mQ;
        redF[8 + w]  = mT;
    }
    __syncthreads();
    if (tid == 0) {
        double bP2 = 0.0, bT2 = 0.0, bPT = 0.0;
        float  bMQ = 0.0f, bMT = 0.0f;
        #pragma unroll
        for (int i = 0; i < 8; i++) {
            bP2 += redD[i];
            bT2 += redD[8 + i];
            bPT += redD[16 + i];
            bMQ = fmaxf(bMQ, redF[i]);
            bMT = fmaxf(bMT, redF[8 + i]);
        }
        atomicAdd(&g_sumP2, bP2);
        atomicAdd(&g_sumT2, bT2);
        atomicAdd(&g_sumPT, bPT);
        atomicMax(&g_maxQ, __float_as_int(bMQ));
        atomicMax(&g_maxT, __float_as_int(bMT));

        __threadfence();
        unsigned prev = atomicAdd(&g_count, 1u);
        if (prev == gridDim.x - 1u) {
            // last block: all other blocks' accumulations are visible
            __threadfence();
            double SP2 = g_sumP2;
            double ST2 = g_sumT2;
            double SPT = g_sumPT;
            double Mp = sqrt((double)__int_as_float(g_maxQ));
            double Mt = (double)__int_as_float(g_maxT);
            // loss = (SP2/Mp^2 - 2*SPT/(Mp*Mt) + ST2/Mt^2) * (Mp*Mt) / sqrt(SP2*ST2)
            double num = SP2 / (Mp * Mp) - 2.0 * SPT / (Mp * Mt) + ST2 / (Mt * Mt);
            out[0] = (float)(num * (Mp * Mt) / sqrt(SP2 * ST2));
            // self-reset for the next graph replay (matches static init state)
            g_sumP2 = 0.0;
            g_sumT2 = 0.0;
            g_sumPT = 0.0;
            g_maxQ  = 0;
            g_maxT  = 0;
            g_count = 0u;
        }
    }
}

extern "C" void kernel_launch(void* const* d_in, const int* in_sizes, int n_in,
                              void* d_out, int out_size)
{
    const float* output  = (const float*)d_in[0];
    const float* targets = (const float*)d_in[1];
    int B = in_sizes[0] / (NS * 3);

    loss_main<<<B, NT>>>(output, targets, (float*)d_out);
}